// round 11
// baseline (speedup 1.0000x reference)
#include <cuda_runtime.h>
#include <math.h>

#define N 256
#define ND (N*N)
#define D 128
#define LAM 1e-3f
#define EPS 1e-3f
#define GRID 128
#define BLK 256

// ---- static scratch ----
__device__ float g_z2s[N*D];
__device__ float g_X[N*2*D], g_Xs[N*2*D];
__device__ float g_n1[N], g_n2[N], g_n2s[N], g_nX[N], g_nXs[N];
__device__ float g_D1[ND], g_Dd[ND], g_Ddd[ND], g_DnA[ND], g_DnB[ND];
__device__ float g_Amat[8][ND];   // 0..3 denom A_s -> U (upper), 4..7 numerator
__device__ float g_Atr[8][ND];    // U^T rows
__device__ float g_invd[8][N];
__device__ float g_Wm[4][ND];
__device__ float g_Mt[4][ND];     // row k = RHS column k of M_s
__device__ float g_bnum[4][N];
__device__ float g_Csol[4][ND];   // row k = solution column k
__device__ float g_xnum[4][N];
__device__ float g_R[ND], g_R2[ND];
__device__ float g_denum[N];

// ---- grid barrier state (sense-reversing; safe across graph replays) ----
__device__ unsigned g_count = 0;
__device__ volatile unsigned g_sense = 0;

__constant__ float c_inv2s2[4] = {0.5f, 5.0e-3f, 5.0e-5f, 5.0e-7f};

__device__ __forceinline__ void gbar() {
    __syncthreads();
    __threadfence();                       // publish this block's writes (gpu scope)
    if (threadIdx.x == 0) {
        unsigned s = g_sense;              // read sense BEFORE arriving
        if (atomicAdd(&g_count, 1u) == GRID - 1u) {
            g_count = 0;
            __threadfence();
            g_sense = s ^ 1u;
        } else {
            while (g_sense == s) { }
        }
    }
    __syncthreads();
    __threadfence();                       // acquire: invalidate stale L1 lines
}

// warp-register 32x32 Cholesky on smem block (lane = column)
__device__ __forceinline__ void factor32(float (*Ub)[65], int o, float* sinv, int lane) {
    float r[32];
    #pragma unroll
    for (int i=0;i<32;i++) r[i]=Ub[o+i][o+lane];
    #pragma unroll
    for (int k=0;k<32;k++) {
        float v = __shfl_sync(0xffffffffu, r[k], k);
        float inv = rsqrtf(fmaxf(v, 1e-30f));
        if (lane == k) { r[k] = v * inv; sinv[o+k] = inv; }
        else if (lane > k) r[k] *= inv;
        #pragma unroll
        for (int i=k+1;i<32;i++) {
            float u = __shfl_sync(0xffffffffu, r[k], i);
            if (lane >= i) r[i] = fmaf(-u, r[k], r[i]);
        }
    }
    #pragma unroll
    for (int i=0;i<32;i++) Ub[o+i][o+lane]=r[i];
}

__global__ void __launch_bounds__(BLK) k_mega(
    const float* __restrict__ z1, const float* __restrict__ z2,
    const int* __restrict__ p1, const int* __restrict__ p2,
    float* __restrict__ out)
{
    __shared__ float pool[4288];          // 16.75KB, aliased per phase
    __shared__ float s_n[8][4];
    __shared__ float s_red[8];
    const int b = blockIdx.x, t = threadIdx.x;
    const int wid = t>>5, lane = t&31;

    // ================= A. gather + norms (2 rows per block) =================
    {
        int row = 2*b + (t>>7);
        int tl = t & 127;
        float a  = z1[row*D+tl],      bb = z2[row*D+tl];
        float as = z1[p1[row]*D+tl],  bs = z2[p2[row]*D+tl];
        g_X [row*2*D+tl] = a;  g_X [row*2*D+D+tl] = bb;
        g_Xs[row*2*D+tl] = as; g_Xs[row*2*D+D+tl] = bs;
        g_z2s[row*D+tl] = bs;
        float v1=a*a,v2=bb*bb,v3=as*as,v4=bs*bs;
        #pragma unroll
        for (int o=16;o;o>>=1){
            v1+=__shfl_down_sync(~0u,v1,o); v2+=__shfl_down_sync(~0u,v2,o);
            v3+=__shfl_down_sync(~0u,v3,o); v4+=__shfl_down_sync(~0u,v4,o);
        }
        if (!lane){ s_n[wid][0]=v1; s_n[wid][1]=v2; s_n[wid][2]=v3; s_n[wid][3]=v4; }
        __syncthreads();
        if (tl==0){
            int wb=(t>>7)*4;
            float n1=s_n[wb][0]+s_n[wb+1][0]+s_n[wb+2][0]+s_n[wb+3][0];
            float n2=s_n[wb][1]+s_n[wb+1][1]+s_n[wb+2][1]+s_n[wb+3][1];
            float n1s=s_n[wb][2]+s_n[wb+1][2]+s_n[wb+2][2]+s_n[wb+3][2];
            float n2s=s_n[wb][3]+s_n[wb+1][3]+s_n[wb+2][3]+s_n[wb+3][3];
            g_n1[row]=n1; g_n2[row]=n2; g_n2s[row]=n2s;
            g_nX[row]=n1+n2; g_nXs[row]=n1s+n2s;
        }
    }
    gbar();

    // ================= B. five distance matrices (320 tile tasks) =================
    {
        float (*As)[33]=(float(*)[33])pool;
        float (*Bs)[33]=(float(*)[33])(pool+32*33);
        int tx=t&15, ty=t>>4, lr=t>>5, lc=t&31;
        for (int task=b; task<320; task+=GRID) {
            int mat=task>>6, tile=task&63;
            int rb=(tile>>3)*32, cb=(tile&7)*32;
            const float *A,*B,*na,*nb; float* om; int K;
            switch (mat) {
                case 0:  A=z1;    B=z2;    na=g_n1;  nb=g_n2;  K=D;   om=g_D1;  break;
                case 1:  A=g_z2s; B=z2;    na=g_n2s; nb=g_n2;  K=D;   om=g_Dd;  break;
                case 2:  A=g_z2s; B=g_z2s; na=g_n2s; nb=g_n2s; K=D;   om=g_Ddd; break;
                case 3:  A=g_X;   B=g_X;   na=g_nX;  nb=g_nX;  K=2*D; om=g_DnA; break;
                default: A=g_X;   B=g_Xs;  na=g_nX;  nb=g_nXs; K=2*D; om=g_DnB; break;
            }
            float a00=0.f,a01=0.f,a10=0.f,a11=0.f;
            for (int kb=0;kb<K;kb+=32){
                __syncthreads();
                #pragma unroll
                for (int i=0;i<32;i+=8){
                    As[lr+i][lc]=A[(rb+lr+i)*K+kb+lc];
                    Bs[lr+i][lc]=B[(cb+lr+i)*K+kb+lc];
                }
                __syncthreads();
                #pragma unroll
                for (int kk=0;kk<32;kk++){
                    float w0=As[ty][kk], w1=As[ty+16][kk];
                    float c0=Bs[tx][kk], c1=Bs[tx+16][kk];
                    a00=fmaf(w0,c0,a00); a01=fmaf(w0,c1,a01);
                    a10=fmaf(w1,c0,a10); a11=fmaf(w1,c1,a11);
                }
            }
            om[(rb+ty   )*N+cb+tx   ]=fmaxf(na[rb+ty   ]+nb[cb+tx   ]-2.f*a00,0.f);
            om[(rb+ty   )*N+cb+tx+16]=fmaxf(na[rb+ty   ]+nb[cb+tx+16]-2.f*a01,0.f);
            om[(rb+ty+16)*N+cb+tx   ]=fmaxf(na[rb+ty+16]+nb[cb+tx   ]-2.f*a10,0.f);
            om[(rb+ty+16)*N+cb+tx+16]=fmaxf(na[rb+ty+16]+nb[cb+tx+16]-2.f*a11,0.f);
        }
    }
    gbar();

    // ================= C. kernel matrices + numerator RHS =================
    {
        for (int i=b*BLK+t; i<ND; i+=GRID*BLK) {
            int r=i>>8, c=i&255;
            float ddd=g_Ddd[i], dna=g_DnA[i], d1=g_D1[i], dd=g_Dd[i];
            float lam_d=(r==c)?LAM:0.f;
            #pragma unroll
            for (int s=0;s<4;s++){
                float cc=c_inv2s2[s];
                g_Amat[s][i]  =expf(-cc*ddd)+lam_d;
                g_Amat[4+s][i]=expf(-cc*dna)+lam_d;
                g_Wm[s][i]=expf(-cc*d1);
                g_Mt[s][c*N+r]=expf(-cc*dd);
            }
        }
        int gw=b*8+wid;                 // exactly 1024 warp tasks
        int s=gw>>8, r=gw&255;
        float e=0.f;
        for (int j=lane;j<N;j+=32) e+=expf(-c_inv2s2[s]*g_DnB[r*N+j]);
        #pragma unroll
        for (int o=16;o;o>>=1) e+=__shfl_down_sync(~0u,e,o);
        if(!lane) g_bnum[s][r]=e;
    }
    gbar();

    // ================= D. blocked Cholesky (PB=64) =================
    for (int pb=0; pb<N; pb+=64) {
        // -- diag-block factor (blocks 0..7, one per matrix) --
        if (b < 8) {
            float (*Ub)[65]=(float(*)[65])pool;
            float* sinv=pool+64*65;
            float* A=g_Amat[b];
            for (int e2=t;e2<64*64;e2+=BLK){int r=e2>>6,c=e2&63; Ub[r][c]=A[(pb+r)*N+pb+c];}
            __syncthreads();
            if (t<32) factor32(Ub,0,sinv,t);
            __syncthreads();
            if (t<32) {
                float x[32];
                #pragma unroll
                for (int i=0;i<32;i++) x[i]=Ub[i][32+t];
                #pragma unroll
                for (int k=0;k<32;k++) {
                    x[k]*=sinv[k];
                    #pragma unroll
                    for (int i=k+1;i<32;i++) x[i]=fmaf(-Ub[k][i],x[k],x[i]);
                }
                #pragma unroll
                for (int i=0;i<32;i++) Ub[i][32+t]=x[i];
            }
            __syncthreads();
            for (int e2=t;e2<1024;e2+=BLK){
                int i2=e2>>5,j2=e2&31;
                float acc=Ub[32+i2][32+j2];
                #pragma unroll
                for (int k=0;k<32;k++) acc=fmaf(-Ub[k][32+i2],Ub[k][32+j2],acc);
                Ub[32+i2][32+j2]=acc;
            }
            __syncthreads();
            if (t<32) factor32(Ub,32,sinv,t);
            __syncthreads();
            for (int e2=t;e2<64*64;e2+=BLK){int r=e2>>6,c=e2&63; A[(pb+r)*N+pb+c]=Ub[r][c];}
            if (t<64) g_invd[b][pb+t]=sinv[t];
        }
        gbar();

        int ncols = N - pb - 64;
        if (ncols > 0) {
            // -- row-panel TRSM: warp per column, full chip --
            {
                int gw=b*8+wid;
                for (int task=gw; task<8*ncols; task+=GRID*8) {
                    int m=task/ncols, col=task-m*ncols;
                    float* A=g_Amat[m];
                    const float* invd=&g_invd[m][pb];
                    int j=pb+64+col;
                    float x0=A[(pb+lane)*N+j];
                    float x1=A[(pb+32+lane)*N+j];
                    float iv0=invd[lane], iv1=invd[32+lane];
                    float u0=A[pb*N+pb+lane];
                    float u1=A[pb*N+pb+32+lane];
                    #pragma unroll 4
                    for (int k=0;k<32;k++){
                        float v=x0*iv0;
                        float xk=__shfl_sync(~0u,v,k);
                        float nu0=u0,nu1=u1;
                        if (k+1<64){ nu0=A[(pb+k+1)*N+pb+lane]; nu1=A[(pb+k+1)*N+pb+32+lane]; }
                        if (lane==k) x0=xk; else if (lane>k) x0=fmaf(-u0,xk,x0);
                        x1=fmaf(-u1,xk,x1);
                        u0=nu0; u1=nu1;
                    }
                    #pragma unroll 4
                    for (int k=32;k<64;k++){
                        int kl=k-32;
                        float v=x1*iv1;
                        float xk=__shfl_sync(~0u,v,kl);
                        float nu1=u1;
                        if (k+1<64) nu1=A[(pb+k+1)*N+pb+32+lane];
                        if (lane==kl) x1=xk; else if (lane>kl) x1=fmaf(-u1,xk,x1);
                        u1=nu1;
                    }
                    A[(pb+lane)*N+j]=x0;
                    A[(pb+32+lane)*N+j]=x1;
                }
            }
            gbar();

            // -- trailing syrk: A22 -= U12^T U12 (upper tiles), full chip --
            {
                int nt=ncols/32, tpm=nt*(nt+1)/2, total=tpm*8;
                float (*Ua)[33]=(float(*)[33])pool;
                float (*Vb)[33]=(float(*)[33])(pool+64*33);
                int tx=t&15, ty=t>>4, lr=t>>5, lc=t&31;
                for (int task=b; task<total; task+=GRID) {
                    int m=task/tpm, tt=task-m*tpm;
                    int i2=0;
                    while (tt >= nt-i2){ tt-=nt-i2; i2++; }
                    int j2=i2+tt;
                    float* A=g_Amat[m];
                    int i0=pb+64+i2*32, j0=pb+64+j2*32;
                    __syncthreads();
                    #pragma unroll
                    for (int i=0;i<64;i+=8){
                        Ua[lr+i][lc]=A[(pb+lr+i)*N+i0+lc];
                        Vb[lr+i][lc]=A[(pb+lr+i)*N+j0+lc];
                    }
                    __syncthreads();
                    float a00=0.f,a01=0.f,a10=0.f,a11=0.f;
                    #pragma unroll
                    for (int kk=0;kk<64;kk++){
                        float w0=Ua[kk][ty], w1=Ua[kk][ty+16];
                        float c0=Vb[kk][tx], c1=Vb[kk][tx+16];
                        a00=fmaf(w0,c0,a00); a01=fmaf(w0,c1,a01);
                        a10=fmaf(w1,c0,a10); a11=fmaf(w1,c1,a11);
                    }
                    A[(i0+ty   )*N+j0+tx   ]-=a00;
                    A[(i0+ty   )*N+j0+tx+16]-=a01;
                    A[(i0+ty+16)*N+j0+tx   ]-=a10;
                    A[(i0+ty+16)*N+j0+tx+16]-=a11;
                }
            }
            gbar();
        }
    }

    // ================= E. transpose U (512 tile tasks) =================
    {
        float (*tile)[33]=(float(*)[33])pool;
        int lr=t>>5, lc=t&31;
        for (int task=b; task<512; task+=GRID) {
            int m=task>>6, tl2=task&63;
            int x0=(tl2&7)*32, y0=(tl2>>3)*32;
            const float* A=g_Amat[m]; float* At=g_Atr[m];
            __syncthreads();
            #pragma unroll
            for (int i=0;i<32;i+=8) tile[lr+i][lc]=A[(y0+lr+i)*N+x0+lc];
            __syncthreads();
            #pragma unroll
            for (int i=0;i<32;i+=8) At[(x0+lr+i)*N+y0+lc]=tile[lc][lr+i];
        }
    }
    gbar();

    // ================= F. big solve: 1028 warp-column tasks =================
    {
        int gw=b*8+wid;
        for (int task=gw; task<1028; task+=GRID*8) {
            const float *U,*L,*invd,*src; float* dst;
            if (task<1024){
                int s=task>>8, col=task&255;
                U=g_Amat[s]; L=g_Atr[s]; invd=g_invd[s];
                src=&g_Mt[s][col*N]; dst=&g_Csol[s][col*N];
            } else {
                int s=task-1024;
                U=g_Amat[4+s]; L=g_Atr[4+s]; invd=g_invd[4+s];
                src=g_bnum[s]; dst=g_xnum[s];
            }
            float x[8], iv[8];
            #pragma unroll
            for (int r=0;r<8;r++){ x[r]=src[r*32+lane]; iv[r]=invd[r*32+lane]; }
            float ub[4][8];
            #pragma unroll
            for (int q=0;q<4;q++)
                #pragma unroll
                for (int r=0;r<8;r++) ub[q][r]=U[q*N + r*32 + lane];
            #pragma unroll
            for (int kr=0;kr<8;kr++) {
                #pragma unroll 1
                for (int kl4=0; kl4<32; kl4+=4) {
                    #pragma unroll
                    for (int q=0;q<4;q++) {
                        int kl=kl4+q;
                        int k=kr*32+kl;
                        float v=x[kr]*iv[kr];
                        float xk=__shfl_sync(~0u,v,kl);
                        if (lane==kl) x[kr]=xk;
                        #pragma unroll
                        for (int r=kr;r<8;r++) {
                            bool act=(r>kr)||(lane>kl);
                            float nx=fmaf(-ub[q][r],xk,x[r]);
                            x[r]=act?nx:x[r];
                        }
                        int kn=k+4;
                        if (kn<N){
                            #pragma unroll
                            for (int r=0;r<8;r++) ub[q][r]=U[kn*N + r*32 + lane];
                        }
                    }
                }
            }
            #pragma unroll
            for (int q=0;q<4;q++)
                #pragma unroll
                for (int r=0;r<8;r++) ub[q][r]=L[(N-4+q)*N + r*32 + lane];
            #pragma unroll
            for (int kr=7;kr>=0;kr--) {
                #pragma unroll 1
                for (int kl4=28; kl4>=0; kl4-=4) {
                    #pragma unroll
                    for (int q=3;q>=0;q--) {
                        int kl=kl4+q;
                        int k=kr*32+kl;
                        float v=x[kr]*iv[kr];
                        float xk=__shfl_sync(~0u,v,kl);
                        if (lane==kl) x[kr]=xk;
                        #pragma unroll
                        for (int r=0;r<=kr;r++) {
                            bool act=(r<kr)||(lane<kl);
                            float nx=fmaf(-ub[q][r],xk,x[r]);
                            x[r]=act?nx:x[r];
                        }
                        int kn=k-4;
                        if (kn>=0){
                            #pragma unroll
                            for (int r=0;r<8;r++) ub[q][r]=L[kn*N + r*32 + lane];
                        }
                    }
                }
            }
            #pragma unroll
            for (int r=0;r<8;r++) dst[r*32+lane]=x[r];
        }
    }
    gbar();

    // ================= G. R = sum_s W_s C_s^T (sigma-split over 128 blocks) =================
    {
        float (*Wa)[33]=(float(*)[33])pool;
        float (*Cb)[33]=(float(*)[33])(pool+32*33);
        int tx=t&15, ty=t>>4, lr=t>>5, lc=t&31;
        int tile2=(b<64)?b:(b-64);
        int sb=(b<64)?0:2;
        float* Rout=(b<64)?g_R:g_R2;
        int rb=(tile2>>3)*32, cb2=(tile2&7)*32;
        float a00=0.f,a01=0.f,a10=0.f,a11=0.f;
        for (int s=sb;s<sb+2;s++){
            const float* Wp=g_Wm[s]; const float* Cp=g_Csol[s];
            for (int kb=0;kb<N;kb+=32){
                __syncthreads();
                #pragma unroll
                for(int i=0;i<32;i+=8){
                    Wa[lr+i][lc]=Wp[(rb+lr+i)*N+kb+lc];
                    Cb[lr+i][lc]=Cp[(cb2+lr+i)*N+kb+lc];
                }
                __syncthreads();
                #pragma unroll
                for (int kk=0;kk<32;kk++){
                    float w0=Wa[ty][kk], w1=Wa[ty+16][kk];
                    float c0=Cb[tx][kk], c1=Cb[tx+16][kk];
                    a00=fmaf(w0,c0,a00); a01=fmaf(w0,c1,a01);
                    a10=fmaf(w1,c0,a10); a11=fmaf(w1,c1,a11);
                }
            }
        }
        Rout[(rb+ty   )*N+cb2+tx   ]=a00;
        Rout[(rb+ty   )*N+cb2+tx+16]=a01;
        Rout[(rb+ty+16)*N+cb2+tx   ]=a10;
        Rout[(rb+ty+16)*N+cb2+tx+16]=a11;
    }
    gbar();

    // ================= H. row sums (warp per row) =================
    {
        int gw=b*8+wid;
        if (gw<N){
            float v=0.f;
            for (int j=lane;j<N;j+=32) v+=fmaxf(g_R[gw*N+j]+g_R2[gw*N+j],0.f);
            #pragma unroll
            for (int o=16;o;o>>=1) v+=__shfl_down_sync(~0u,v,o);
            if(!lane) g_denum[gw]=0.25f*v+(float)N*EPS;
        }
    }
    gbar();

    // ================= I. loss (block 0) =================
    if (b==0){
        float est=fmaxf(0.25f*(g_xnum[0][t]+g_xnum[1][t]+g_xnum[2][t]+g_xnum[3][t]),0.f)+EPS;
        float v=logf(g_denum[t])+logf(est);
        #pragma unroll
        for (int o=16;o;o>>=1) v+=__shfl_down_sync(~0u,v,o);
        if(!lane) s_red[wid]=v;
        __syncthreads();
        if (t==0){
            float s0=0.f;
            #pragma unroll
            for (int w=0;w<8;w++) s0+=s_red[w];
            out[0]=s0;
        }
    }
}

extern "C" void kernel_launch(void* const* d_in, const int* in_sizes, int n_in,
                              void* d_out, int out_size) {
    const float* z1=(const float*)d_in[0];
    const float* z2=(const float*)d_in[1];
    const int*   p1=(const int*)d_in[2];
    const int*   p2=(const int*)d_in[3];
    float* out=(float*)d_out;
    k_mega<<<GRID, BLK>>>(z1, z2, p1, p2, out);
}

// round 12
// speedup vs baseline: 1.7409x; 1.7409x over previous
#include <cuda_runtime.h>
#include <math.h>

#define N 256
#define ND (N*N)
#define D 128
#define LAM 1e-3f
#define EPS 1e-3f

// ---- static scratch ----
__device__ float g_z2s[N*D];
__device__ float g_X[N*2*D], g_Xs[N*2*D];
__device__ float g_n1[N], g_n2[N], g_n2s[N], g_nX[N], g_nXs[N];
__device__ float g_D1[ND], g_Dd[ND], g_Ddd[ND], g_DnA[ND], g_DnB[ND];
__device__ float g_Amat[8][ND];   // 0..3 denom A_s -> U (upper), 4..7 numerator
__device__ float g_Atr[8][ND];    // U^T rows (for backward solve)
__device__ float g_invd[8][N];
__device__ float g_Wm[4][ND];
__device__ float g_Mt[4][ND];     // row k = RHS column k of M_s
__device__ float g_bnum[4][N];
__device__ float g_Csol[4][ND];   // row k = solution column k
__device__ float g_xnum[4][N];
__device__ float g_R[ND];
__device__ float g_denum[N];

__constant__ float c_inv2s2[4] = {0.5f, 5.0e-3f, 5.0e-5f, 5.0e-7f};

// ---------- 1. gather + norms ----------
__global__ void k_gather(const float* __restrict__ z1, const float* __restrict__ z2,
                         const int* __restrict__ p1, const int* __restrict__ p2) {
    int i = blockIdx.x, t = threadIdx.x; // 128
    float a  = z1[i*D+t],      b  = z2[i*D+t];
    float as = z1[p1[i]*D+t],  bs = z2[p2[i]*D+t];
    g_X [i*2*D+t] = a;  g_X [i*2*D+D+t] = b;
    g_Xs[i*2*D+t] = as; g_Xs[i*2*D+D+t] = bs;
    g_z2s[i*D+t] = bs;
    float v1=a*a, v2=b*b, v3=as*as, v4=bs*bs;
    #pragma unroll
    for (int o=16;o;o>>=1){
        v1+=__shfl_down_sync(~0u,v1,o); v2+=__shfl_down_sync(~0u,v2,o);
        v3+=__shfl_down_sync(~0u,v3,o); v4+=__shfl_down_sync(~0u,v4,o);
    }
    __shared__ float s1[4],s2[4],s3[4],s4[4];
    int w=t>>5;
    if(!(t&31)){s1[w]=v1;s2[w]=v2;s3[w]=v3;s4[w]=v4;}
    __syncthreads();
    if(t==0){
        float n1=s1[0]+s1[1]+s1[2]+s1[3], n2=s2[0]+s2[1]+s2[2]+s2[3];
        float n1s=s3[0]+s3[1]+s3[2]+s3[3], n2s=s4[0]+s4[1]+s4[2]+s4[3];
        g_n1[i]=n1; g_n2[i]=n2; g_n2s[i]=n2s; g_nX[i]=n1+n2; g_nXs[i]=n1s+n2s;
    }
}

// ---------- 2. five squared-distance matrices ----------
__global__ void k_dist(const float* __restrict__ z1, const float* __restrict__ z2) {
    const float *A,*B,*na,*nb; float* out; int K;
    switch (blockIdx.z) {
        case 0:  A=z1;    B=z2;    na=g_n1;  nb=g_n2;  K=D;   out=g_D1;  break;
        case 1:  A=g_z2s; B=z2;    na=g_n2s; nb=g_n2;  K=D;   out=g_Dd;  break;
        case 2:  A=g_z2s; B=g_z2s; na=g_n2s; nb=g_n2s; K=D;   out=g_Ddd; break;
        case 3:  A=g_X;   B=g_X;   na=g_nX;  nb=g_nX;  K=2*D; out=g_DnA; break;
        default: A=g_X;   B=g_Xs;  na=g_nX;  nb=g_nXs; K=2*D; out=g_DnB; break;
    }
    __shared__ float As[32][33], Bs[32][33];
    int tx=threadIdx.x, ty=threadIdx.y;
    int row=blockIdx.y*32+ty, col=blockIdx.x*32+tx;
    float acc=0.f;
    for (int kb=0; kb<K; kb+=32) {
        As[ty][tx]=A[row*K+kb+tx];
        Bs[ty][tx]=B[(blockIdx.x*32+ty)*K+kb+tx];
        __syncthreads();
        #pragma unroll
        for (int kk=0; kk<32; kk++) acc=fmaf(As[ty][kk],Bs[tx][kk],acc);
        __syncthreads();
    }
    out[row*N+col]=fmaxf(na[row]+nb[col]-2.f*acc,0.f);
}

// ---------- 3. kernel matrices ----------
__global__ void k_build() {
    int r=blockIdx.x, s=blockIdx.y, t=threadIdx.x;  // block 256
    float c=c_inv2s2[s];
    float lam_d=(t==r)?LAM:0.f;
    g_Amat[s  ][r*N+t]=expf(-c*g_Ddd[r*N+t])+lam_d;
    g_Amat[4+s][r*N+t]=expf(-c*g_DnA[r*N+t])+lam_d;
    g_Wm[s][r*N+t]=expf(-c*g_D1[r*N+t]);
    g_Mt[s][t*N+r]=expf(-c*g_Dd[r*N+t]);
    float e=expf(-c*g_DnB[r*N+t]);
    #pragma unroll
    for (int o=16;o;o>>=1) e+=__shfl_down_sync(~0u,e,o);
    __shared__ float sr[8];
    if(!(t&31)) sr[t>>5]=e;
    __syncthreads();
    if(t==0){ float s0=0.f;
        #pragma unroll
        for(int w=0;w<8;w++) s0+=sr[w];
        g_bnum[s][r]=s0; }
}

// ---------- 4a. diag-block factor 64x64: all 256 threads, no shfl ----------
// Thread t owns rows [rg*16, rg*16+16) of column j, rg=t>>6, j=t&63, in registers.
__global__ void __launch_bounds__(256) k_pfact(int pb) {
    int m = blockIdx.x;
    float* A = g_Amat[m];
    __shared__ float srow[64];
    int t = threadIdx.x;
    int j = t & 63, rg = t >> 6;
    int r0 = rg * 16;
    float acc[16];
    #pragma unroll
    for (int r=0;r<16;r++) acc[r] = A[(pb+r0+r)*N + pb + j];

    for (int k=0;k<64;k++) {
        __syncthreads();
        if (rg == (k>>4)) srow[j] = acc[k & 15];   // publish unscaled row k
        __syncthreads();
        float pv  = fmaxf(srow[k], 1e-30f);
        float inv = rsqrtf(pv);
        if (rg == (k>>4)) {
            acc[k & 15] *= inv;                    // finalize row k in owner regs
            if (j == k) g_invd[m][pb+k] = inv;
        }
        float sj = srow[j] * (inv*inv);            // srow[j]/pivot
        float4 s0 = *(const float4*)&srow[r0];
        float4 s1 = *(const float4*)&srow[r0+4];
        float4 s2 = *(const float4*)&srow[r0+8];
        float4 s3 = *(const float4*)&srow[r0+12];
        float sv[16] = {s0.x,s0.y,s0.z,s0.w, s1.x,s1.y,s1.z,s1.w,
                        s2.x,s2.y,s2.z,s2.w, s3.x,s3.y,s3.z,s3.w};
        #pragma unroll
        for (int r=0;r<16;r++)
            if (r0 + r > k) acc[r] = fmaf(-sv[r], sj, acc[r]);
    }
    __syncthreads();
    #pragma unroll
    for (int r=0;r<16;r++) A[(pb+r0+r)*N + pb + j] = acc[r];
}

// ---------- 4b. panel TRSM: U12 = U11^{-T} A12, warp per column, full chip ----------
__global__ void __launch_bounds__(256) k_ptrsm(int pb) {
    int m = blockIdx.y;
    int wid = threadIdx.x>>5, lane = threadIdx.x&31;
    int col = blockIdx.x*8 + wid;
    int ncols = N - pb - 64;
    if (col >= ncols) return;
    float* A = g_Amat[m];
    const float* invd = &g_invd[m][pb];
    int j = pb + 64 + col;

    float x0 = A[(pb + lane)*N + j];
    float x1 = A[(pb + 32 + lane)*N + j];
    float iv0 = invd[lane], iv1 = invd[32+lane];
    float u0 = A[pb*N + pb + lane];
    float u1 = A[pb*N + pb + 32 + lane];
    #pragma unroll 4
    for (int k=0;k<32;k++) {
        float v = x0*iv0;
        float xk = __shfl_sync(~0u, v, k);
        float nu0=u0, nu1=u1;
        if (k+1<64) {
            nu0 = A[(pb+k+1)*N + pb + lane];
            nu1 = A[(pb+k+1)*N + pb + 32 + lane];
        }
        if (lane==k) x0=xk;
        else if (lane>k) x0=fmaf(-u0,xk,x0);
        x1=fmaf(-u1,xk,x1);
        u0=nu0; u1=nu1;
    }
    #pragma unroll 4
    for (int k=32;k<64;k++) {
        int kl=k-32;
        float v = x1*iv1;
        float xk = __shfl_sync(~0u, v, kl);
        float nu1=u1;
        if (k+1<64) nu1 = A[(pb+k+1)*N + pb + 32 + lane];
        if (lane==kl) x1=xk;
        else if (lane>kl) x1=fmaf(-u1,xk,x1);
        u1=nu1;
    }
    A[(pb + lane)*N + j] = x0;
    A[(pb + 32 + lane)*N + j] = x1;
}

// ---------- 4c. trailing syrk: A22 -= U12^T U12, full-chip ----------
__global__ void __launch_bounds__(256) k_syrk(int pb) {
    if ((int)blockIdx.y > (int)blockIdx.x) return;   // upper tiles only
    float* A = g_Amat[blockIdx.z];
    int i0 = pb + 64 + blockIdx.y*32, j0 = pb + 64 + blockIdx.x*32;
    __shared__ float Ua[64][33], Vb[64][33];
    int t=threadIdx.x, tx=t&15, ty=t>>4;
    int lr=t>>5, lc=t&31;
    #pragma unroll
    for (int i=0;i<64;i+=8) {
        Ua[lr+i][lc]=A[(pb+lr+i)*N + i0 + lc];
        Vb[lr+i][lc]=A[(pb+lr+i)*N + j0 + lc];
    }
    __syncthreads();
    float a00=0.f,a01=0.f,a10=0.f,a11=0.f;
    #pragma unroll
    for (int k=0;k<64;k++) {
        float w0=Ua[k][ty], w1=Ua[k][ty+16];
        float c0=Vb[k][tx], c1=Vb[k][tx+16];
        a00=fmaf(w0,c0,a00); a01=fmaf(w0,c1,a01);
        a10=fmaf(w1,c0,a10); a11=fmaf(w1,c1,a11);
    }
    A[(i0+ty   )*N + j0+tx   ] -= a00;
    A[(i0+ty   )*N + j0+tx+16] -= a01;
    A[(i0+ty+16)*N + j0+tx   ] -= a10;
    A[(i0+ty+16)*N + j0+tx+16] -= a11;
}

// ---------- 5. transpose U ----------
__global__ void k_transpose() {
    __shared__ float tile[32][33];
    const float* A=g_Amat[blockIdx.z]; float* At=g_Atr[blockIdx.z];
    int tx=threadIdx.x, ty=threadIdx.y;              // (32,8)
    int x0=blockIdx.x*32, y0=blockIdx.y*32;
    #pragma unroll
    for(int i=0;i<32;i+=8) tile[ty+i][tx]=A[(y0+ty+i)*N+x0+tx];
    __syncthreads();
    #pragma unroll
    for(int i=0;i<32;i+=8) At[(x0+ty+i)*N+y0+tx]=tile[tx][ty+i];
}

// ---------- 6. register-resident TRSM, warp per column, 4-deep prefetch ----------
__global__ void __launch_bounds__(256) k_trsm() {
    int s=blockIdx.y, t=threadIdx.x, wid=t>>5, lane=t&31;
    const float *U,*L,*invd,*src; float* dst;
    if (blockIdx.x<32) {
        int col=blockIdx.x*8+wid;
        U=g_Amat[s]; L=g_Atr[s]; invd=g_invd[s];
        src=&g_Mt[s][col*N]; dst=&g_Csol[s][col*N];
    } else {
        if (wid) return;
        U=g_Amat[4+s]; L=g_Atr[4+s]; invd=g_invd[4+s];
        src=g_bnum[s]; dst=g_xnum[s];
    }
    float x[8], iv[8];
    #pragma unroll
    for (int r=0;r<8;r++){ x[r]=src[r*32+lane]; iv[r]=invd[r*32+lane]; }

    float ub[4][8];
    #pragma unroll
    for (int q=0;q<4;q++)
        #pragma unroll
        for (int r=0;r<8;r++) ub[q][r]=U[q*N + r*32 + lane];

    #pragma unroll
    for (int kr=0;kr<8;kr++) {
        #pragma unroll 1
        for (int kl4=0; kl4<32; kl4+=4) {
            #pragma unroll
            for (int q=0;q<4;q++) {
                int kl = kl4 + q;
                int k  = kr*32 + kl;
                float v = x[kr]*iv[kr];
                float xk = __shfl_sync(~0u, v, kl);
                if (lane==kl) x[kr]=xk;
                #pragma unroll
                for (int r=kr;r<8;r++) {
                    bool act = (r>kr) || (lane>kl);
                    float nx = fmaf(-ub[q][r], xk, x[r]);
                    x[r] = act ? nx : x[r];
                }
                int kn = k+4;
                if (kn < N) {
                    #pragma unroll
                    for (int r=0;r<8;r++) ub[q][r] = U[kn*N + r*32 + lane];
                }
            }
        }
    }
    #pragma unroll
    for (int q=0;q<4;q++)
        #pragma unroll
        for (int r=0;r<8;r++) ub[q][r]=L[(N-4+q)*N + r*32 + lane];

    #pragma unroll
    for (int kr=7;kr>=0;kr--) {
        #pragma unroll 1
        for (int kl4=28; kl4>=0; kl4-=4) {
            #pragma unroll
            for (int q=3;q>=0;q--) {
                int kl = kl4 + q;
                int k  = kr*32 + kl;
                float v = x[kr]*iv[kr];
                float xk = __shfl_sync(~0u, v, kl);
                if (lane==kl) x[kr]=xk;
                #pragma unroll
                for (int r=0;r<=kr;r++) {
                    bool act = (r<kr) || (lane<kl);
                    float nx = fmaf(-ub[q][r], xk, x[r]);
                    x[r] = act ? nx : x[r];
                }
                int kn = k-4;
                if (kn >= 0) {
                    #pragma unroll
                    for (int r=0;r<8;r++) ub[q][r] = L[kn*N + r*32 + lane];
                }
            }
        }
    }
    #pragma unroll
    for (int r=0;r<8;r++) dst[r*32+lane] = x[r];
}

// ---------- 7. R = sum_s W_s * C_s^T ----------
__global__ void k_gemmR() {
    __shared__ float Wa[32][33], Cb[32][33];
    int t=threadIdx.x;                                // 256
    int tx=t&15, ty=t>>4;
    int rb=blockIdx.y*32, cb=blockIdx.x*32;
    int lr=t>>5, lc=t&31;
    float a00=0.f,a01=0.f,a10=0.f,a11=0.f;
    for (int s=0;s<4;s++) {
        const float* Wp=g_Wm[s]; const float* Cp=g_Csol[s];
        for (int kb=0;kb<N;kb+=32) {
            __syncthreads();
            #pragma unroll
            for(int i=0;i<32;i+=8){
                Wa[lr+i][lc]=Wp[(rb+lr+i)*N+kb+lc];
                Cb[lr+i][lc]=Cp[(cb+lr+i)*N+kb+lc];
            }
            __syncthreads();
            #pragma unroll
            for (int kk=0;kk<32;kk++) {
                float w0=Wa[ty][kk], w1=Wa[ty+16][kk];
                float c0=Cb[tx][kk], c1=Cb[tx+16][kk];
                a00=fmaf(w0,c0,a00); a01=fmaf(w0,c1,a01);
                a10=fmaf(w1,c0,a10); a11=fmaf(w1,c1,a11);
            }
        }
    }
    g_R[(rb+ty   )*N+cb+tx   ]=a00;
    g_R[(rb+ty   )*N+cb+tx+16]=a01;
    g_R[(rb+ty+16)*N+cb+tx   ]=a10;
    g_R[(rb+ty+16)*N+cb+tx+16]=a11;
}

// ---------- 8. row sums ----------
__global__ void k_rowsum() {
    int i=blockIdx.x, t=threadIdx.x;
    float v=fmaxf(g_R[i*N+t],0.f);
    #pragma unroll
    for(int o=16;o;o>>=1) v+=__shfl_down_sync(~0u,v,o);
    __shared__ float sr[8];
    if(!(t&31)) sr[t>>5]=v;
    __syncthreads();
    if(t==0){ float s0=0.f;
        #pragma unroll
        for(int w=0;w<8;w++) s0+=sr[w];
        g_denum[i]=0.25f*s0+(float)N*EPS; }
}

// ---------- 9. loss ----------
__global__ void k_loss(float* __restrict__ out) {
    int t=threadIdx.x;
    float est=fmaxf(0.25f*(g_xnum[0][t]+g_xnum[1][t]+g_xnum[2][t]+g_xnum[3][t]),0.f)+EPS;
    float v=logf(g_denum[t])+logf(est);
    #pragma unroll
    for(int o=16;o;o>>=1) v+=__shfl_down_sync(~0u,v,o);
    __shared__ float sr[8];
    if(!(t&31)) sr[t>>5]=v;
    __syncthreads();
    if(t==0){ float s0=0.f;
        #pragma unroll
        for(int w=0;w<8;w++) s0+=sr[w];
        out[0]=s0; }
}

extern "C" void kernel_launch(void* const* d_in, const int* in_sizes, int n_in,
                              void* d_out, int out_size) {
    const float* z1=(const float*)d_in[0];
    const float* z2=(const float*)d_in[1];
    const int*   p1=(const int*)d_in[2];
    const int*   p2=(const int*)d_in[3];
    float* out=(float*)d_out;

    k_gather<<<N,128>>>(z1,z2,p1,p2);
    k_dist<<<dim3(8,8,5),dim3(32,32)>>>(z1,z2);
    k_build<<<dim3(N,4),N>>>();

    k_pfact<<<8,256>>>(0);
    k_ptrsm<<<dim3(24,8),256>>>(0);
    k_syrk<<<dim3(6,6,8),256>>>(0);
    k_pfact<<<8,256>>>(64);
    k_ptrsm<<<dim3(16,8),256>>>(64);
    k_syrk<<<dim3(4,4,8),256>>>(64);
    k_pfact<<<8,256>>>(128);
    k_ptrsm<<<dim3(8,8),256>>>(128);
    k_syrk<<<dim3(2,2,8),256>>>(128);
    k_pfact<<<8,256>>>(192);

    k_transpose<<<dim3(8,8,8),dim3(32,8)>>>();
    k_trsm<<<dim3(33,4),256>>>();
    k_gemmR<<<dim3(8,8),256>>>();
    k_rowsum<<<N,N>>>();
    k_loss<<<1,N>>>(out);
}